// round 5
// baseline (speedup 1.0000x reference)
#include <cuda_runtime.h>

// out = inputs * (noise >= 0.5f ? 2.0f : 0.0f)
// Persistent grid-stride: one wave exactly (1184 blocks x 256 threads),
// zero wave transitions. Plain cached LDG.128/STG.128 (hints measured harmful).
// 16,777,216 float4 total; 1184*256 = 303,104 threads; n_vec4 % threads != 0,
// so grid-stride loop with bounds check (uniform across warp, coalesced).

__global__ void __launch_bounds__(256)
sparse_dropout_persist(const float4* __restrict__ inputs,
                       const float4* __restrict__ noise,
                       float4* __restrict__ out,
                       int n_vec4)
{
    const unsigned stride = gridDim.x * blockDim.x;

    for (unsigned idx = blockIdx.x * blockDim.x + threadIdx.x;
         idx < (unsigned)n_vec4; idx += stride)
    {
        float4 x = inputs[idx];
        float4 n = noise[idx];

        float4 r;
        r.x = (n.x >= 0.5f) ? x.x * 2.0f : 0.0f;
        r.y = (n.y >= 0.5f) ? x.y * 2.0f : 0.0f;
        r.z = (n.z >= 0.5f) ? x.z * 2.0f : 0.0f;
        r.w = (n.w >= 0.5f) ? x.w * 2.0f : 0.0f;

        out[idx] = r;
    }
}

extern "C" void kernel_launch(void* const* d_in, const int* in_sizes, int n_in,
                              void* d_out, int out_size)
{
    const float4* inputs = (const float4*)d_in[0];
    const float4* noise  = (const float4*)d_in[1];
    float4* out          = (float4*)d_out;

    const int n_vec4 = out_size / 4;  // 16,777,216

    // One full wave on GB300: 152 SMs, 256 thr/CTA, 8 CTAs/SM (2048 thr/SM).
    const int threads = 256;
    const int blocks = 152 * 8;       // 1216

    sparse_dropout_persist<<<blocks, threads>>>(inputs, noise, out, n_vec4);
}

// round 6
// speedup vs baseline: 1.1063x; 1.1063x over previous
#include <cuda_runtime.h>

// out = inputs * (noise >= 0.5f ? 2.0f : 0.0f)
// FINAL: flat one-float4-per-thread, 512-thread blocks, default caching.
// 67,108,864 fp32 = 16,777,216 float4 = 32768 blocks * 512 threads, exact.
//
// Measured across 5 structural variants (VPT 1/2/4, cache hints, persistent
// grid-stride): this flat launch is fastest at 88% DRAM utilization
// (~6.97 TB/s) — the HBM3e ceiling for a 2:1 read/write interleaved stream.
// Compute pipes <7%; traffic (768 MiB) is mandatory. This is the roofline.

__global__ void __launch_bounds__(512)
sparse_dropout_vec4_b512(const float4* __restrict__ inputs,
                         const float4* __restrict__ noise,
                         float4* __restrict__ out)
{
    const unsigned idx = blockIdx.x * blockDim.x + threadIdx.x;

    float4 x = inputs[idx];
    float4 n = noise[idx];

    float4 r;
    r.x = (n.x >= 0.5f) ? x.x * 2.0f : 0.0f;
    r.y = (n.y >= 0.5f) ? x.y * 2.0f : 0.0f;
    r.z = (n.z >= 0.5f) ? x.z * 2.0f : 0.0f;
    r.w = (n.w >= 0.5f) ? x.w * 2.0f : 0.0f;

    out[idx] = r;
}

extern "C" void kernel_launch(void* const* d_in, const int* in_sizes, int n_in,
                              void* d_out, int out_size)
{
    const float4* inputs = (const float4*)d_in[0];
    const float4* noise  = (const float4*)d_in[1];
    float4* out          = (float4*)d_out;

    const int n_vec4 = out_size / 4;     // 16,777,216
    const int threads = 512;
    const int blocks = n_vec4 / threads; // 32768, exact

    sparse_dropout_vec4_b512<<<blocks, threads>>>(inputs, noise, out);
}